// round 16
// baseline (speedup 1.0000x reference)
#include <cuda_runtime.h>
#include <cuda_bf16.h>
#include <cstdint>
#include <math.h>

// ---------------- problem constants ----------------
#define TSTEPS 512
#define BATCH  64
#define DIN    1024
#define DHID   1024

// ---------------- persistent-loop config ----------------
#define NCTA 128                 // persistent CTAs; CTA owns 8 hidden dims = 32 gemm cols
#define NTHR 512                 // 16 warps: mg=wid&1, ng=(wid>>1)&1, ks=wid>>2
#define NCHL 16                  // recurrent K chunks (1024/64)

// loop SMEM layout (bytes)
#define ZSTG    8192             // per stage per group: zhi 4K | zlo 4K (32 rows x 128B)
#define NSTG    3
#define ASTG_OFF 0                                   // A stages 3x8K
#define BSTG_OFF (NSTG * ZSTG)                       // 24576: B stages 3x8K
#define WOFF     (2 * NSTG * ZSTG)                   // 49152: W_h resident 128KB
#define PP_STRIDE 34
#define PP_SLICE2 (32 * PP_STRIDE)                   // 1088 floats per k-slice (32 rows)
#define PP_OFF   (WOFF + 131072)                     // 180224: pp [4][1088] = 17408B
#define C_OFF    (PP_OFF + 17408)                    // 197632: c state 512 floats
#define BIAS_OFF (C_OFF + 2048)                      // 199680: 32 floats
#define LEN_OFF  (BIAS_OFF + 128)                    // 199808: 64 ints
#define TGT_OFF  (LEN_OFF + 256)                     // 200064: tgt[2]
#define HST_OFF  (TGT_OFF + 16)                      // 200080: h staging 1KB
#define SMEM_LOOP (HST_OFF + 1024)                   // 201104

// precompute GEMM smem: 2 stages x (A 4x16KB + B 32KB)
#define PSTG_BYTES 98304
#define SMEM_PRE   (2 * PSTG_BYTES)

#define PX_ROWB 2112             // floats per (t,cta) px block: 64 rows x 33

// ---------------- device-global scratch (static; no cudaMalloc) ----------------
__device__ __align__(16) unsigned char g_zx[(size_t)TSTEPS*16*16384];  // x tiles [t*16+ch][hi8K|lo8K]
// h tiles: [group][buf][chl][hi4K|lo4K] (32 rows x 128B per group)
__device__ __align__(16) unsigned char g_zh2[(size_t)2*2*16*8192];
__device__ __align__(16) unsigned char g_Wxt[(size_t)32*16*32768];     // Wx tiles [ng*16+ch][hi16K|lo16K]
__device__ __align__(16) unsigned char g_Wht[(size_t)NCTA*NCHL*8192];  // Wh tiles [cta*16+ch][hi4K|lo4K]
__device__ float g_px[(size_t)TSTEPS*NCTA*PX_ROWB];                    // x-projection [t][cta][b*33+c]
__device__ unsigned long long g_bar;        // init grid barrier
__device__ unsigned long long g_barG[2];    // per-group step barriers (monotonic)

// ---------------- helpers ----------------
__host__ __device__ __forceinline__ uint32_t swz128(uint32_t x) { return x ^ ((x >> 3) & 0x70); }

__device__ __forceinline__ uint32_t smem_u32(const void* p) {
    uint32_t a;
    asm("{ .reg .u64 t; cvta.to.shared.u64 t, %1; cvt.u32.u64 %0, t; }" : "=r"(a) : "l"(p));
    return a;
}
union U4 { unsigned short s[8]; uint4 v; };
__device__ __forceinline__ void bf16split(float v, unsigned short& hi, unsigned short& lo) {
    __nv_bfloat16 h = __float2bfloat16_rn(v);
    float r = v - __bfloat162float(h);
    __nv_bfloat16 l = __float2bfloat16_rn(r);
    hi = reinterpret_cast<unsigned short&>(h);
    lo = reinterpret_cast<unsigned short&>(l);
}
__device__ __forceinline__ unsigned short bf16hi(float v) {
    __nv_bfloat16 h = __float2bfloat16_rn(v);
    return reinterpret_cast<unsigned short&>(h);
}
__device__ __forceinline__ void cp16(uint32_t saddr, const void* gaddr) {
    asm volatile("cp.async.cg.shared.global [%0], [%1], 16;" :: "r"(saddr), "l"(gaddr));
}
__device__ __forceinline__ void cp_commit() { asm volatile("cp.async.commit_group;"); }
template <int N> __device__ __forceinline__ void cp_wait() {
    asm volatile("cp.async.wait_group %0;" :: "n"(N));
}
__device__ __forceinline__ void ldsm4(uint32_t& r0, uint32_t& r1, uint32_t& r2, uint32_t& r3, uint32_t a) {
    asm volatile("ldmatrix.sync.aligned.m8n8.x4.shared.b16 {%0,%1,%2,%3}, [%4];"
                 : "=r"(r0), "=r"(r1), "=r"(r2), "=r"(r3) : "r"(a));
}
__device__ __forceinline__ void ldsm2(uint32_t& r0, uint32_t& r1, uint32_t a) {
    asm volatile("ldmatrix.sync.aligned.m8n8.x2.shared.b16 {%0,%1}, [%2];"
                 : "=r"(r0), "=r"(r1) : "r"(a));
}
__device__ __forceinline__ void mma16816(float* d, uint32_t a0, uint32_t a1, uint32_t a2, uint32_t a3,
                                         uint32_t b0, uint32_t b1) {
    asm volatile("mma.sync.aligned.m16n8k16.row.col.f32.bf16.bf16.f32 "
                 "{%0,%1,%2,%3}, {%4,%5,%6,%7}, {%8,%9}, {%0,%1,%2,%3};"
                 : "+f"(d[0]), "+f"(d[1]), "+f"(d[2]), "+f"(d[3])
                 : "r"(a0), "r"(a1), "r"(a2), "r"(a3), "r"(b0), "r"(b1));
}
__device__ __forceinline__ void grid_sync_full() {
    __syncthreads();
    if (threadIdx.x == 0) {
        __threadfence();
        unsigned long long t = atomicAdd(&g_bar, 1ULL);
        unsigned long long target = (t / NCTA + 1ULL) * NCTA;
        while (*(volatile unsigned long long*)&g_bar < target) __nanosleep(64);
        __threadfence();
    }
    __syncthreads();
}
__device__ __forceinline__ float sigmoidf_(float x) { return 1.0f / (1.0f + expf(-x)); }

// ============ init 1: x -> pre-swizzled bf16 hi/lo SW128 tiles ============
__global__ void cvt_x_kernel(const float* __restrict__ batch) {
    int bid = blockIdx.x;                 // t*16 + ch
    int tid = threadIdx.x;                // 128
    int b = tid >> 1, half = tid & 1;
    int t = bid >> 4, ch = bid & 15;
    const float* src = batch + ((size_t)t * BATCH + b) * DIN + ch * 64 + half * 32;
    unsigned char* dhi = g_zx + (size_t)bid * 16384;
    unsigned char* dlo = dhi + 8192;
    #pragma unroll
    for (int q = 0; q < 4; ++q) {
        float v[8];
        *(float4*)&v[0] = *(const float4*)(src + q * 8);
        *(float4*)&v[4] = *(const float4*)(src + q * 8 + 4);
        U4 hi, lo;
        #pragma unroll
        for (int j = 0; j < 8; ++j) bf16split(v[j], hi.s[j], lo.s[j]);
        uint32_t off = swz128((uint32_t)b * 128 + (uint32_t)(half * 4 + q) * 16);
        *(uint4*)(dhi + off) = hi.v;
        *(uint4*)(dlo + off) = lo.v;
    }
}

// ============ init 2 (FUSED): W_x tiles (bid<512) + W_h tiles (bid>=512) ============
__global__ void cvt_w_kernel(const float* __restrict__ Wi, const float* __restrict__ Wf,
                             const float* __restrict__ Wc, const float* __restrict__ Wo) {
    __shared__ float sraw[4][64][8];
    const float* Wsrc[4] = {Wi, Wf, Wc, Wo};
    int tid = threadIdx.x;                // 256
    if (blockIdx.x < 512) {
        int bid = blockIdx.x;             // ng*16 + ch
        int ng = bid >> 4, ch = bid & 15;
        int j = tid >> 1, khalf = tid & 1;
        int q = j >> 5, c = j & 31, gate = c >> 3;
        int wcol = (4 * ng + q) * 8 + (c & 7);
        const float* src = Wsrc[gate] + (size_t)(ch * 64 + khalf * 32) * DHID + wcol;
        unsigned char* dst = g_Wxt + (size_t)bid * 32768;
        #pragma unroll
        for (int qq = 0; qq < 4; ++qq) {
            U4 hi, lo;
            #pragma unroll
            for (int kk = 0; kk < 8; ++kk)
                bf16split(src[(size_t)(qq * 8 + kk) * DHID], hi.s[kk], lo.s[kk]);
            uint32_t off = swz128((uint32_t)j * 128 + (uint32_t)(khalf * 4 + qq) * 16);
            *(uint4*)(dst + off) = hi.v;
            *(uint4*)(dst + 16384 + off) = lo.v;
        }
    } else {
        int bid = blockIdx.x - 512;       // cta*16 + ch
        int cta = bid >> 4, ch = bid & 15;
        {
            int g = tid >> 6, kk = tid & 63;
            const float* s = Wsrc[g] + (size_t)(1024 + ch * 64 + kk) * DHID + cta * 8;
            float4 a = *(const float4*)s, b = *(const float4*)(s + 4);
            sraw[g][kk][0] = a.x; sraw[g][kk][1] = a.y; sraw[g][kk][2] = a.z; sraw[g][kk][3] = a.w;
            sraw[g][kk][4] = b.x; sraw[g][kk][5] = b.y; sraw[g][kk][6] = b.z; sraw[g][kk][7] = b.w;
        }
        __syncthreads();
        int c = tid >> 3, kkb = tid & 7;
        int g = c >> 3, dd = c & 7;
        U4 hi, lo;
        #pragma unroll
        for (int j = 0; j < 8; ++j) bf16split(sraw[g][kkb * 8 + j][dd], hi.s[j], lo.s[j]);
        unsigned char* dst = g_Wht + (size_t)bid * 8192;
        uint32_t off = swz128((uint32_t)c * 128 + (uint32_t)kkb * 16);
        *(uint4*)(dst + off) = hi.v;
        *(uint4*)(dst + 4096 + off) = lo.v;
    }
}

// ============ precompute GEMM: px[t][cta][b,32c] = x_t @ W_x (3-term split) ============
__global__ __launch_bounds__(256, 1)
void gemm_x_kernel() {
    extern __shared__ __align__(1024) unsigned char sm[];
    const uint32_t smem = smem_u32(sm);
    const int ng = blockIdx.x;
    const int tg = blockIdx.y;
    const int tid = threadIdx.x, wid = tid >> 5, lane = tid & 31;
    const int mt = wid & 3;
    const int nh = wid >> 2;
    const int lane16 = lane & 15;
    const int usel_a = lane >> 4;
    const int usel_b = (lane16 >> 3) & 1;

    int aoff[4][4];
    #pragma unroll
    for (int mi = 0; mi < 4; ++mi) {
        int arow = mi * 16 + lane16, arx = (arow & 7) << 4;
        #pragma unroll
        for (int ks = 0; ks < 4; ++ks)
            aoff[mi][ks] = arow * 128 + ((32 * ks + 16 * usel_a) ^ arx);
    }
    int boff[8][4];
    #pragma unroll
    for (int ni = 0; ni < 8; ++ni) {
        int brow = nh * 64 + ni * 8 + (lane16 & 7), brx = (brow & 7) << 4;
        #pragma unroll
        for (int ks = 0; ks < 4; ++ks)
            boff[ni][ks] = brow * 128 + ((32 * ks + 16 * usel_b) ^ brx);
    }

    float acc[4][8][4];
    #pragma unroll
    for (int mi = 0; mi < 4; ++mi)
        #pragma unroll
        for (int ni = 0; ni < 8; ++ni)
            #pragma unroll
            for (int q = 0; q < 4; ++q) acc[mi][ni][q] = 0.0f;

    auto issueP = [&](int ch) {
        uint32_t sb = smem + (uint32_t)(ch & 1) * PSTG_BYTES;
        #pragma unroll
        for (int i = 0; i < 16; ++i) {
            int j = tid + i * 256;
            int tt = j >> 10, off = j & 1023;
            cp16(sb + tt * 16384 + off * 16,
                 g_zx + ((size_t)(tg * 4 + tt) * 16 + ch) * 16384 + off * 16);
        }
        #pragma unroll
        for (int i = 0; i < 8; ++i) {
            int j = tid + i * 256;
            cp16(sb + 65536 + j * 16, g_Wxt + ((size_t)(ng * 16 + ch)) * 32768 + j * 16);
        }
        cp_commit();
    };

    issueP(0);
    for (int ch = 0; ch < 16; ++ch) {
        if (ch + 1 < 16) { issueP(ch + 1); cp_wait<1>(); }
        else             cp_wait<0>();
        __syncthreads();
        uint32_t sb  = smem + (uint32_t)(ch & 1) * PSTG_BYTES;
        uint32_t zhi = sb + mt * 16384, zlo = zhi + 8192;
        uint32_t bhi = sb + 65536, blo = bhi + 16384;
        #pragma unroll
        for (int ks = 0; ks < 4; ++ks) {
            uint32_t zh[4][4], zl[4][4], wf[8][2];
            #pragma unroll
            for (int mi = 0; mi < 4; ++mi) ldsm4(zh[mi][0], zh[mi][1], zh[mi][2], zh[mi][3], zhi + aoff[mi][ks]);
            #pragma unroll
            for (int ni = 0; ni < 8; ++ni) ldsm2(wf[ni][0], wf[ni][1], bhi + boff[ni][ks]);
            #pragma unroll
            for (int mi = 0; mi < 4; ++mi)
                #pragma unroll
                for (int ni = 0; ni < 8; ++ni)
                    mma16816(acc[mi][ni], zh[mi][0], zh[mi][1], zh[mi][2], zh[mi][3], wf[ni][0], wf[ni][1]);
            #pragma unroll
            for (int mi = 0; mi < 4; ++mi) ldsm4(zl[mi][0], zl[mi][1], zl[mi][2], zl[mi][3], zlo + aoff[mi][ks]);
            #pragma unroll
            for (int mi = 0; mi < 4; ++mi)
                #pragma unroll
                for (int ni = 0; ni < 8; ++ni)
                    mma16816(acc[mi][ni], zl[mi][0], zl[mi][1], zl[mi][2], zl[mi][3], wf[ni][0], wf[ni][1]);
            #pragma unroll
            for (int ni = 0; ni < 8; ++ni) ldsm2(wf[ni][0], wf[ni][1], blo + boff[ni][ks]);
            #pragma unroll
            for (int mi = 0; mi < 4; ++mi)
                #pragma unroll
                for (int ni = 0; ni < 8; ++ni)
                    mma16816(acc[mi][ni], zh[mi][0], zh[mi][1], zh[mi][2], zh[mi][3], wf[ni][0], wf[ni][1]);
        }
        __syncthreads();
    }

    const int t = tg * 4 + mt;
    #pragma unroll
    for (int mi = 0; mi < 4; ++mi) {
        int r0 = mi * 16 + (lane >> 2);
        #pragma unroll
        for (int ni = 0; ni < 8; ++ni) {
            int j = nh * 64 + ni * 8 + (lane & 3) * 2;
            int q = j >> 5, c = j & 31;
            float* base = g_px + ((size_t)t * NCTA + 4 * ng + q) * PX_ROWB;
            base[r0 * 33 + c]           = acc[mi][ni][0];
            base[r0 * 33 + c + 1]       = acc[mi][ni][1];
            base[(r0 + 8) * 33 + c]     = acc[mi][ni][2];
            base[(r0 + 8) * 33 + c + 1] = acc[mi][ni][3];
        }
    }
}

// ============ h tile writer (init only) ============
__device__ __forceinline__ void store_h_init(int cta, int b, const float* h8) {
    int grp = b >> 5, row = b & 31;
    int chl = cta >> 3, kkb = cta & 7;
    U4 hi, lo;
    #pragma unroll
    for (int j = 0; j < 8; ++j) bf16split(h8[j], hi.s[j], lo.s[j]);
    uint32_t off = swz128((uint32_t)row * 128 + (uint32_t)kkb * 16);
    unsigned char* base = g_zh2 + (((size_t)grp * 2 + 0) * 16 + chl) * 8192;  // buf 0
    *(uint4*)(base + off) = hi.v;
    *(uint4*)(base + 4096 + off) = lo.v;
}

// ============ persistent recurrent kernel: split-batch ping-pong ============
__global__ __launch_bounds__(NTHR, 1)
void lstm_mma_kernel(const int* __restrict__ lengths, const float* __restrict__ c0,
                     const float* __restrict__ bi, const float* __restrict__ bff,
                     const float* __restrict__ bc, const float* __restrict__ bo,
                     float* __restrict__ out) {
    extern __shared__ __align__(1024) unsigned char sm[];
    const uint32_t smem = smem_u32(sm);
    float* pp_s   = (float*)(sm + PP_OFF);     // [4][32*34]
    float* c_s    = (float*)(sm + C_OFF);      // [512]
    float* bias_s = (float*)(sm + BIAS_OFF);   // [32]
    int*   len_s  = (int*)(sm + LEN_OFF);      // [64]
    volatile unsigned long long* tgt_s = (volatile unsigned long long*)(sm + TGT_OFF);  // [2]
    unsigned short* hst = (unsigned short*)(sm + HST_OFF);  // hi[32][8] | lo[32][8]

    const int tid = threadIdx.x, wid = tid >> 5, lane = tid & 31;
    const int cta = blockIdx.x;
    const int dbase = cta * 8;

    // warp roles: mg = m16 half (0..1), ngh = n16 half (0..1), ks = k16 residue (0..3)
    const int mg = wid & 1, ngh = (wid >> 1) & 1, ks = wid >> 2;
    const int lane16 = lane & 15;
    const int usel_a = lane >> 4;
    const int usel_b = (lane16 >> 3) & 1;
    int aoff, boff[2];
    {
        int arow = mg * 16 + lane16, arx = (arow & 7) << 4;
        aoff = arow * 128 + ((32 * ks + 16 * usel_a) ^ arx);
    }
    #pragma unroll
    for (int ni = 0; ni < 2; ++ni) {
        int brow = ngh * 16 + ni * 8 + (lane16 & 7), brx = (brow & 7) << 4;
        boff[ni] = brow * 128 + ((32 * ks + 16 * usel_b) ^ brx);
    }

    // epilogue coordinates (tid < 256): bb = row within group, dd = hidden dim
    const int bb = (tid & 255) >> 3, dd = tid & 7;
    const int chl = cta >> 3, kkb = cta & 7;

    // ---- init: W_h -> SMEM (resident) ----
    {
        const unsigned char* wsrc = g_Wht + (size_t)cta * (NCHL * 8192);
        for (int i = tid; i < 8192; i += NTHR) cp16(smem + WOFF + i * 16, wsrc + (size_t)i * 16);
        cp_commit(); cp_wait<0>();
    }
    for (int j = tid; j < 512; j += NTHR) c_s[j] = c0[dbase + (j & 7)];
    if (tid < 32) bias_s[tid] = ((tid >> 3) == 0 ? bi : (tid >> 3) == 1 ? bff :
                                 (tid >> 3) == 2 ? bc : bo)[dbase + (tid & 7)];
    if (tid < BATCH) {
        len_s[tid] = lengths[tid];
        float h0[8];
        #pragma unroll
        for (int d = 0; d < 8; ++d) h0[d] = tanhf(c0[dbase + d]);
        store_h_init(cta, tid, h0);
    }
    if (tid == 0) { tgt_s[0] = 0ULL; tgt_s[1] = 0ULL; }
    grid_sync_full();

    // ---- recurrence: A phase (batches 0-31) then B phase (32-63) each step ----
    for (int t = 0; t < TSTEPS; ++t) {
        const int buf = t & 1;

        #pragma unroll 1
        for (int grp = 0; grp < 2; ++grp) {
            const uint32_t stg_base = smem + (grp ? BSTG_OFF : ASTG_OFF);
            const unsigned char* hsrc_base = g_zh2 + (((size_t)grp * 2 + buf) * 16) * 8192;

            // px prefetch for this phase (no h dependency)
            float pxr[4];
            if (tid < 256) {
                const float* p = g_px + ((size_t)t * NCTA + cta) * PX_ROWB
                               + (grp * 32 + bb) * 33 + dd;
                #pragma unroll
                for (int g = 0; g < 4; ++g) pxr[g] = __ldg(p + g * 8);
            }

            // wait: this group's step t-1 h from all CTAs (published one phase ago -> hidden)
            if (tid == 0) {
                unsigned long long tgt = tgt_s[grp];
                while (*(volatile unsigned long long*)&g_barG[grp] < tgt) __nanosleep(32);
                __threadfence();
            }
            __syncthreads();

            auto issue = [&](int i) {
                const int ci = (chl + i) & 15;
                const unsigned char* srcz = hsrc_base + (size_t)ci * 8192;
                uint32_t sb = stg_base + (uint32_t)(i % NSTG) * ZSTG;
                cp16(sb + tid * 16, srcz + (size_t)tid * 16);
                cp_commit();
            };

            float acc[2][4];
            #pragma unroll
            for (int ni = 0; ni < 2; ++ni)
                #pragma unroll
                for (int q = 0; q < 4; ++q) acc[ni][q] = 0.0f;

            issue(0); issue(1);
            for (int i = 0; i < NCHL; ++i) {
                if (i < NCHL - 1) cp_wait<1>();
                else              cp_wait<0>();
                __syncthreads();
                if (i + 2 < NCHL) issue(i + 2);

                const int ci = (chl + i) & 15;
                const uint32_t zb  = stg_base + (uint32_t)(i % NSTG) * ZSTG;
                const uint32_t zhi = zb, zlo = zb + 4096;
                const uint32_t whi = smem + WOFF + (uint32_t)ci * 8192, wlo = whi + 4096;

                uint32_t ah[4], al[4], bh[2][2], bl[2][2];
                ldsm4(ah[0], ah[1], ah[2], ah[3], zhi + aoff);
                ldsm4(al[0], al[1], al[2], al[3], zlo + aoff);
                #pragma unroll
                for (int ni = 0; ni < 2; ++ni) {
                    ldsm2(bh[ni][0], bh[ni][1], whi + boff[ni]);
                    ldsm2(bl[ni][0], bl[ni][1], wlo + boff[ni]);
                }
                #pragma unroll
                for (int ni = 0; ni < 2; ++ni) {
                    mma16816(acc[ni], ah[0], ah[1], ah[2], ah[3], bh[ni][0], bh[ni][1]);
                    mma16816(acc[ni], ah[0], ah[1], ah[2], ah[3], bl[ni][0], bl[ni][1]);
                    mma16816(acc[ni], al[0], al[1], al[2], al[3], bh[ni][0], bh[ni][1]);
                }
            }

            // ---- gather K-split partials (slice ks; rows mg*16.., cols ngh*16..) ----
            {
                float* pp = pp_s + ks * PP_SLICE2;
                int r0 = mg * 16 + (lane >> 2);
                #pragma unroll
                for (int ni = 0; ni < 2; ++ni) {
                    int c = ngh * 16 + ni * 8 + (lane & 3) * 2;
                    *(float2*)&pp[r0 * PP_STRIDE + c]       = make_float2(acc[ni][0], acc[ni][1]);
                    *(float2*)&pp[(r0 + 8) * PP_STRIDE + c] = make_float2(acc[ni][2], acc[ni][3]);
                }
            }
            __syncthreads();

            // ---- epilogue: 256 threads, 1 cell each ----
            float hval = 0.0f;
            if (tid < 256) {
                const int bglob = grp * 32 + bb;
                const int myl = len_s[bglob];
                const int bo34 = bb * PP_STRIDE;
                float pre[4];
                #pragma unroll
                for (int g = 0; g < 4; ++g) {
                    const int c = g * 8 + dd;
                    pre[g] = pxr[g] + bias_s[c]
                           + pp_s[bo34 + c] + pp_s[PP_SLICE2 + bo34 + c]
                           + pp_s[2 * PP_SLICE2 + bo34 + c] + pp_s[3 * PP_SLICE2 + bo34 + c];
                }
                float ig = sigmoidf_(pre[0]), fg = sigmoidf_(pre[1]);
                float gg = tanhf(pre[2]),     og = sigmoidf_(pre[3]);
                float cn = fg * c_s[bglob * 8 + dd] + ig * gg;
                float h  = og * tanhf(cn);
                if (t >= myl) h = 0.0f;
                c_s[bglob * 8 + dd] = cn;
                __nv_bfloat16 hb = __float2bfloat16_rn(h);
                hst[bb * 8 + dd]       = reinterpret_cast<unsigned short&>(hb);
                hst[256 + bb * 8 + dd] = bf16hi(h - __bfloat162float(hb));
                hval = h;
            }
            __syncthreads();

            // ---- wide h publish: 64 threads x uint4 ----
            if (tid < 64) {
                int which = tid >> 5, row = tid & 31;        // 0=hi, 1=lo
                uint4 v = *(uint4*)(hst + which * 256 + row * 8);
                unsigned char* base = g_zh2 + (((size_t)grp * 2 + (buf ^ 1)) * 16 + chl) * 8192
                                    + which * 4096;
                *(uint4*)(base + swz128((uint32_t)row * 128 + (uint32_t)kkb * 16)) = v;
            }
            __syncthreads();
            if (tid == 0) {    // arrive for this group
                __threadfence();
                unsigned long long my = atomicAdd(&g_barG[grp], 1ULL);
                tgt_s[grp] = (my / NCTA + 1ULL) * NCTA;
            }
            // output store: off the critical path
            if (tid < 256)
                out[((size_t)t * BATCH + grp * 32 + bb) * DHID + dbase + dd] = hval;
        }
    }
}

extern "C" void kernel_launch(void* const* d_in, const int* in_sizes, int n_in,
                              void* d_out, int out_size) {
    const float* batch   = (const float*)d_in[0];
    const int*   lengths = (const int*)  d_in[1];
    const float* c0      = (const float*)d_in[2];
    const float* Wi = (const float*)d_in[3];
    const float* bi = (const float*)d_in[4];
    const float* Wf = (const float*)d_in[5];
    const float* bf = (const float*)d_in[6];
    const float* Wc = (const float*)d_in[7];
    const float* bc = (const float*)d_in[8];
    const float* Wo = (const float*)d_in[9];
    const float* bo = (const float*)d_in[10];
    float* out = (float*)d_out;

    cvt_x_kernel<<<TSTEPS * 16, 128>>>(batch);
    cvt_w_kernel<<<512 + NCTA * NCHL, 256>>>(Wi, Wf, Wc, Wo);

    cudaFuncSetAttribute(gemm_x_kernel, cudaFuncAttributeMaxDynamicSharedMemorySize, SMEM_PRE);
    gemm_x_kernel<<<dim3(32, 128), 256, SMEM_PRE>>>();

    cudaFuncSetAttribute(lstm_mma_kernel, cudaFuncAttributeMaxDynamicSharedMemorySize, SMEM_LOOP);
    lstm_mma_kernel<<<NCTA, NTHR, SMEM_LOOP>>>(lengths, c0, bi, bf, bc, bo, out);
}

// round 17
// speedup vs baseline: 1.3251x; 1.3251x over previous
#include <cuda_runtime.h>
#include <cuda_bf16.h>
#include <cstdint>
#include <math.h>

// ---------------- problem constants ----------------
#define TSTEPS 512
#define BATCH  64
#define DIN    1024
#define DHID   1024

// ---------------- persistent-loop config ----------------
#define NCTA 128                 // persistent CTAs; CTA owns 8 hidden dims = 32 gemm cols
#define NTHR 512                 // 16 warps: mg = wid&3 (m16 group), kslice = wid>>2
#define NCHL 16                  // recurrent K chunks (1024/64)

// loop SMEM layout (bytes)
#define ZSTG    16384            // per stage: zhi 8K | zlo 8K
#define NSTG    6                // DEEP pipeline: prefetch distance 5
#define WOFF    (NSTG * ZSTG)                // 98304 : W_h resident 128KB
#define PP_STRIDE 34
#define PP_SLICE  (BATCH * PP_STRIDE)        // 2176 floats per k-slice
// pp [4][2176] = 34816 B — ALIASES stage region (post-loop, sync-guarded)
#define C_OFF   (WOFF + 131072)              // 229376: c state 512 floats
#define BIAS_OFF (C_OFF + 2048)              // 231424: 32 floats
#define LEN_OFF (BIAS_OFF + 128)             // 231552: 64 ints
#define TGT_OFF (LEN_OFF + 256)              // 231808
#define SMEM_LOOP (TGT_OFF + 16)             // 231824 (<= 232448 cap)

// precompute GEMM smem: 2 stages x (A 4x16KB + B 32KB)
#define PSTG_BYTES 98304
#define SMEM_PRE   (2 * PSTG_BYTES)

#define PX_ROWB 2112             // floats per (t,cta) px block: 64 rows x 33

// ---------------- device-global scratch (static; no cudaMalloc) ----------------
__device__ __align__(16) unsigned char g_zx[(size_t)TSTEPS*16*16384];  // x tiles [t*16+ch][hi8K|lo8K]
__device__ __align__(16) unsigned char g_zh[(size_t)2*16*16384];       // h tiles [buf*16+chl][hi8K|lo8K]
__device__ __align__(16) unsigned char g_Wxt[(size_t)32*16*32768];     // Wx tiles [ng*16+ch][hi16K|lo16K]
__device__ __align__(16) unsigned char g_Wht[(size_t)NCTA*NCHL*8192];  // Wh tiles [cta*16+ch][hi4K|lo4K]
__device__ float g_px[(size_t)TSTEPS*NCTA*PX_ROWB];                    // x-projection [t][cta][b*33+c]
__device__ unsigned long long g_bar;   // monotonic grid-barrier ticket

// ---------------- helpers ----------------
__host__ __device__ __forceinline__ uint32_t swz128(uint32_t x) { return x ^ ((x >> 3) & 0x70); }

__device__ __forceinline__ uint32_t smem_u32(const void* p) {
    uint32_t a;
    asm("{ .reg .u64 t; cvta.to.shared.u64 t, %1; cvt.u32.u64 %0, t; }" : "=r"(a) : "l"(p));
    return a;
}
union U4 { unsigned short s[8]; uint4 v; };
__device__ __forceinline__ void bf16split(float v, unsigned short& hi, unsigned short& lo) {
    __nv_bfloat16 h = __float2bfloat16_rn(v);
    float r = v - __bfloat162float(h);
    __nv_bfloat16 l = __float2bfloat16_rn(r);
    hi = reinterpret_cast<unsigned short&>(h);
    lo = reinterpret_cast<unsigned short&>(l);
}
__device__ __forceinline__ unsigned short bf16hi(float v) {
    __nv_bfloat16 h = __float2bfloat16_rn(v);
    return reinterpret_cast<unsigned short&>(h);
}
__device__ __forceinline__ void cp16(uint32_t saddr, const void* gaddr) {
    asm volatile("cp.async.cg.shared.global [%0], [%1], 16;" :: "r"(saddr), "l"(gaddr));
}
__device__ __forceinline__ void cp_commit() { asm volatile("cp.async.commit_group;"); }
template <int N> __device__ __forceinline__ void cp_wait() {
    asm volatile("cp.async.wait_group %0;" :: "n"(N));
}
__device__ __forceinline__ void ldsm4(uint32_t& r0, uint32_t& r1, uint32_t& r2, uint32_t& r3, uint32_t a) {
    asm volatile("ldmatrix.sync.aligned.m8n8.x4.shared.b16 {%0,%1,%2,%3}, [%4];"
                 : "=r"(r0), "=r"(r1), "=r"(r2), "=r"(r3) : "r"(a));
}
__device__ __forceinline__ void ldsm2(uint32_t& r0, uint32_t& r1, uint32_t a) {
    asm volatile("ldmatrix.sync.aligned.m8n8.x2.shared.b16 {%0,%1}, [%2];"
                 : "=r"(r0), "=r"(r1) : "r"(a));
}
__device__ __forceinline__ void mma16816(float* d, uint32_t a0, uint32_t a1, uint32_t a2, uint32_t a3,
                                         uint32_t b0, uint32_t b1) {
    asm volatile("mma.sync.aligned.m16n8k16.row.col.f32.bf16.bf16.f32 "
                 "{%0,%1,%2,%3}, {%4,%5,%6,%7}, {%8,%9}, {%0,%1,%2,%3};"
                 : "+f"(d[0]), "+f"(d[1]), "+f"(d[2]), "+f"(d[3])
                 : "r"(a0), "r"(a1), "r"(a2), "r"(a3), "r"(b0), "r"(b1));
}
__device__ __forceinline__ void grid_sync_full() {
    __syncthreads();
    if (threadIdx.x == 0) {
        __threadfence();
        unsigned long long t = atomicAdd(&g_bar, 1ULL);
        unsigned long long target = (t / NCTA + 1ULL) * NCTA;
        while (*(volatile unsigned long long*)&g_bar < target) __nanosleep(64);
        __threadfence();
    }
    __syncthreads();
}
__device__ __forceinline__ float sigmoidf_(float x) { return 1.0f / (1.0f + expf(-x)); }

// ============ init 1: x -> pre-swizzled bf16 hi/lo SW128 tiles ============
__global__ void cvt_x_kernel(const float* __restrict__ batch) {
    int bid = blockIdx.x;                 // t*16 + ch
    int tid = threadIdx.x;                // 128
    int b = tid >> 1, half = tid & 1;
    int t = bid >> 4, ch = bid & 15;
    const float* src = batch + ((size_t)t * BATCH + b) * DIN + ch * 64 + half * 32;
    unsigned char* dhi = g_zx + (size_t)bid * 16384;
    unsigned char* dlo = dhi + 8192;
    #pragma unroll
    for (int q = 0; q < 4; ++q) {
        float v[8];
        *(float4*)&v[0] = *(const float4*)(src + q * 8);
        *(float4*)&v[4] = *(const float4*)(src + q * 8 + 4);
        U4 hi, lo;
        #pragma unroll
        for (int j = 0; j < 8; ++j) bf16split(v[j], hi.s[j], lo.s[j]);
        uint32_t off = swz128((uint32_t)b * 128 + (uint32_t)(half * 4 + q) * 16);
        *(uint4*)(dhi + off) = hi.v;
        *(uint4*)(dlo + off) = lo.v;
    }
}

// ============ init 2 (FUSED): W_x tiles (bid<512) + W_h tiles (bid>=512) ============
__global__ void cvt_w_kernel(const float* __restrict__ Wi, const float* __restrict__ Wf,
                             const float* __restrict__ Wc, const float* __restrict__ Wo) {
    __shared__ float sraw[4][64][8];
    const float* Wsrc[4] = {Wi, Wf, Wc, Wo};
    int tid = threadIdx.x;                // 256
    if (blockIdx.x < 512) {
        int bid = blockIdx.x;             // ng*16 + ch
        int ng = bid >> 4, ch = bid & 15;
        int j = tid >> 1, khalf = tid & 1;
        int q = j >> 5, c = j & 31, gate = c >> 3;
        int wcol = (4 * ng + q) * 8 + (c & 7);
        const float* src = Wsrc[gate] + (size_t)(ch * 64 + khalf * 32) * DHID + wcol;
        unsigned char* dst = g_Wxt + (size_t)bid * 32768;
        #pragma unroll
        for (int qq = 0; qq < 4; ++qq) {
            U4 hi, lo;
            #pragma unroll
            for (int kk = 0; kk < 8; ++kk)
                bf16split(src[(size_t)(qq * 8 + kk) * DHID], hi.s[kk], lo.s[kk]);
            uint32_t off = swz128((uint32_t)j * 128 + (uint32_t)(khalf * 4 + qq) * 16);
            *(uint4*)(dst + off) = hi.v;
            *(uint4*)(dst + 16384 + off) = lo.v;
        }
    } else {
        int bid = blockIdx.x - 512;       // cta*16 + ch
        int cta = bid >> 4, ch = bid & 15;
        {
            int g = tid >> 6, kk = tid & 63;
            const float* s = Wsrc[g] + (size_t)(1024 + ch * 64 + kk) * DHID + cta * 8;
            float4 a = *(const float4*)s, b = *(const float4*)(s + 4);
            sraw[g][kk][0] = a.x; sraw[g][kk][1] = a.y; sraw[g][kk][2] = a.z; sraw[g][kk][3] = a.w;
            sraw[g][kk][4] = b.x; sraw[g][kk][5] = b.y; sraw[g][kk][6] = b.z; sraw[g][kk][7] = b.w;
        }
        __syncthreads();
        int c = tid >> 3, kkb = tid & 7;
        int g = c >> 3, dd = c & 7;
        U4 hi, lo;
        #pragma unroll
        for (int j = 0; j < 8; ++j) bf16split(sraw[g][kkb * 8 + j][dd], hi.s[j], lo.s[j]);
        unsigned char* dst = g_Wht + (size_t)bid * 8192;
        uint32_t off = swz128((uint32_t)c * 128 + (uint32_t)kkb * 16);
        *(uint4*)(dst + off) = hi.v;
        *(uint4*)(dst + 4096 + off) = lo.v;
    }
}

// ============ precompute GEMM: px[t][cta][b,32c] = x_t @ W_x (3-term split) ============
__global__ __launch_bounds__(256, 1)
void gemm_x_kernel() {
    extern __shared__ __align__(1024) unsigned char sm[];
    const uint32_t smem = smem_u32(sm);
    const int ng = blockIdx.x;
    const int tg = blockIdx.y;
    const int tid = threadIdx.x, wid = tid >> 5, lane = tid & 31;
    const int mt = wid & 3;
    const int nh = wid >> 2;
    const int lane16 = lane & 15;
    const int usel_a = lane >> 4;
    const int usel_b = (lane16 >> 3) & 1;

    int aoff[4][4];
    #pragma unroll
    for (int mi = 0; mi < 4; ++mi) {
        int arow = mi * 16 + lane16, arx = (arow & 7) << 4;
        #pragma unroll
        for (int ks = 0; ks < 4; ++ks)
            aoff[mi][ks] = arow * 128 + ((32 * ks + 16 * usel_a) ^ arx);
    }
    int boff[8][4];
    #pragma unroll
    for (int ni = 0; ni < 8; ++ni) {
        int brow = nh * 64 + ni * 8 + (lane16 & 7), brx = (brow & 7) << 4;
        #pragma unroll
        for (int ks = 0; ks < 4; ++ks)
            boff[ni][ks] = brow * 128 + ((32 * ks + 16 * usel_b) ^ brx);
    }

    float acc[4][8][4];
    #pragma unroll
    for (int mi = 0; mi < 4; ++mi)
        #pragma unroll
        for (int ni = 0; ni < 8; ++ni)
            #pragma unroll
            for (int q = 0; q < 4; ++q) acc[mi][ni][q] = 0.0f;

    auto issueP = [&](int ch) {
        uint32_t sb = smem + (uint32_t)(ch & 1) * PSTG_BYTES;
        #pragma unroll
        for (int i = 0; i < 16; ++i) {
            int j = tid + i * 256;
            int tt = j >> 10, off = j & 1023;
            cp16(sb + tt * 16384 + off * 16,
                 g_zx + ((size_t)(tg * 4 + tt) * 16 + ch) * 16384 + off * 16);
        }
        #pragma unroll
        for (int i = 0; i < 8; ++i) {
            int j = tid + i * 256;
            cp16(sb + 65536 + j * 16, g_Wxt + ((size_t)(ng * 16 + ch)) * 32768 + j * 16);
        }
        cp_commit();
    };

    issueP(0);
    for (int ch = 0; ch < 16; ++ch) {
        if (ch + 1 < 16) { issueP(ch + 1); cp_wait<1>(); }
        else             cp_wait<0>();
        __syncthreads();
        uint32_t sb  = smem + (uint32_t)(ch & 1) * PSTG_BYTES;
        uint32_t zhi = sb + mt * 16384, zlo = zhi + 8192;
        uint32_t bhi = sb + 65536, blo = bhi + 16384;
        #pragma unroll
        for (int ks = 0; ks < 4; ++ks) {
            uint32_t zh[4][4], zl[4][4], wf[8][2];
            #pragma unroll
            for (int mi = 0; mi < 4; ++mi) ldsm4(zh[mi][0], zh[mi][1], zh[mi][2], zh[mi][3], zhi + aoff[mi][ks]);
            #pragma unroll
            for (int ni = 0; ni < 8; ++ni) ldsm2(wf[ni][0], wf[ni][1], bhi + boff[ni][ks]);
            #pragma unroll
            for (int mi = 0; mi < 4; ++mi)
                #pragma unroll
                for (int ni = 0; ni < 8; ++ni)
                    mma16816(acc[mi][ni], zh[mi][0], zh[mi][1], zh[mi][2], zh[mi][3], wf[ni][0], wf[ni][1]);
            #pragma unroll
            for (int mi = 0; mi < 4; ++mi) ldsm4(zl[mi][0], zl[mi][1], zl[mi][2], zl[mi][3], zlo + aoff[mi][ks]);
            #pragma unroll
            for (int mi = 0; mi < 4; ++mi)
                #pragma unroll
                for (int ni = 0; ni < 8; ++ni)
                    mma16816(acc[mi][ni], zl[mi][0], zl[mi][1], zl[mi][2], zl[mi][3], wf[ni][0], wf[ni][1]);
            #pragma unroll
            for (int ni = 0; ni < 8; ++ni) ldsm2(wf[ni][0], wf[ni][1], blo + boff[ni][ks]);
            #pragma unroll
            for (int mi = 0; mi < 4; ++mi)
                #pragma unroll
                for (int ni = 0; ni < 8; ++ni)
                    mma16816(acc[mi][ni], zh[mi][0], zh[mi][1], zh[mi][2], zh[mi][3], wf[ni][0], wf[ni][1]);
        }
        __syncthreads();
    }

    const int t = tg * 4 + mt;
    #pragma unroll
    for (int mi = 0; mi < 4; ++mi) {
        int r0 = mi * 16 + (lane >> 2);
        #pragma unroll
        for (int ni = 0; ni < 8; ++ni) {
            int j = nh * 64 + ni * 8 + (lane & 3) * 2;
            int q = j >> 5, c = j & 31;
            float* base = g_px + ((size_t)t * NCTA + 4 * ng + q) * PX_ROWB;
            base[r0 * 33 + c]           = acc[mi][ni][0];
            base[r0 * 33 + c + 1]       = acc[mi][ni][1];
            base[(r0 + 8) * 33 + c]     = acc[mi][ni][2];
            base[(r0 + 8) * 33 + c + 1] = acc[mi][ni][3];
        }
    }
}

// ============ h tile writer (init only; epilogue writes per-thread) ============
__device__ __forceinline__ void store_h_tiles(int nbuf, int cta, int b, const float* h8) {
    int chl = cta >> 3, kkb = cta & 7;
    U4 hi, lo;
    #pragma unroll
    for (int j = 0; j < 8; ++j) bf16split(h8[j], hi.s[j], lo.s[j]);
    uint32_t off = swz128((uint32_t)b * 128 + (uint32_t)kkb * 16);
    unsigned char* base = g_zh + ((size_t)nbuf * 16 + chl) * 16384;
    *(uint4*)(base + off) = hi.v;
    *(uint4*)(base + 8192 + off) = lo.v;
}

// ============ persistent recurrent kernel: 16 warps, DEEP 6-stage pipeline ============
__global__ __launch_bounds__(NTHR, 1)
void lstm_mma_kernel(const int* __restrict__ lengths, const float* __restrict__ c0,
                     const float* __restrict__ bi, const float* __restrict__ bff,
                     const float* __restrict__ bc, const float* __restrict__ bo,
                     float* __restrict__ out) {
    extern __shared__ __align__(1024) unsigned char sm[];
    const uint32_t smem = smem_u32(sm);
    float* pp_s   = (float*)sm;                // [4][2176] — ALIASES stage region (post-loop)
    float* c_s    = (float*)(sm + C_OFF);      // [512]
    float* bias_s = (float*)(sm + BIAS_OFF);   // [32]
    int*   len_s  = (int*)(sm + LEN_OFF);      // [64]
    volatile unsigned long long* tgt_s = (volatile unsigned long long*)(sm + TGT_OFF);

    const int tid = threadIdx.x, wid = tid >> 5, lane = tid & 31;
    const int cta = blockIdx.x;
    const int dbase = cta * 8;

    // warp roles: mg = m16 group (0..3), kslice = k16 residue (0..3)
    const int mg = wid & 3, kslice = wid >> 2;
    const int lane16 = lane & 15;
    const int usel_a = lane >> 4;
    const int usel_b = (lane16 >> 3) & 1;
    int aoff, boff[4];
    {
        int arow = mg * 16 + lane16, arx = (arow & 7) << 4;
        aoff = arow * 128 + ((32 * kslice + 16 * usel_a) ^ arx);
    }
    #pragma unroll
    for (int ni = 0; ni < 4; ++ni) {
        int brow = ni * 8 + (lane16 & 7), brx = (brow & 7) << 4;
        boff[ni] = brow * 128 + ((32 * kslice + 16 * usel_b) ^ brx);
    }

    // epilogue coordinates: 1 cell per thread
    const int b = tid >> 3, dd = tid & 7;
    const int chl = cta >> 3, kkb = cta & 7;

    // ---- init: W_h -> SMEM (resident) ----
    {
        const unsigned char* wsrc = g_Wht + (size_t)cta * (NCHL * 8192);
        for (int i = tid; i < 8192; i += NTHR) cp16(smem + WOFF + i * 16, wsrc + (size_t)i * 16);
        cp_commit(); cp_wait<0>();
    }
    for (int j = tid; j < 512; j += NTHR) c_s[j] = c0[dbase + (j & 7)];
    if (tid < 32) bias_s[tid] = ((tid >> 3) == 0 ? bi : (tid >> 3) == 1 ? bff :
                                 (tid >> 3) == 2 ? bc : bo)[dbase + (tid & 7)];
    if (tid < BATCH) {
        len_s[tid] = lengths[tid];
        float h0[8];
        #pragma unroll
        for (int d = 0; d < 8; ++d) h0[d] = tanhf(c0[dbase + d]);
        store_h_tiles(0, cta, tid, h0);
    }
    if (tid == 0) *tgt_s = 0ULL;   // step-0 wait passes immediately
    grid_sync_full();

    // ---- recurrence ----
    for (int t = 0; t < TSTEPS; ++t) {
        const int buf = t & 1;

        // px prefetch into registers (no h dependency; consumed at epilogue)
        float pxr[4];
        {
            const float* p = g_px + ((size_t)t * NCTA + cta) * PX_ROWB + b * 33 + dd;
            #pragma unroll
            for (int g = 0; g < 4; ++g) pxr[g] = __ldg(p + g * 8);
        }

        // wait for all CTAs' step t-1 h (tid0 poll + fence, block consumer pattern)
        if (tid == 0) {
            unsigned long long tgt = *tgt_s;
            while (*(volatile unsigned long long*)&g_bar < tgt) __nanosleep(32);
            __threadfence();
        }
        __syncthreads();   // also orders prev-step pp reads before stage refill (alias guard)

        // stage chunk for iteration i (rotated id); 2 cp16/thread
        auto issue = [&](int i) {
            const int ci = (chl + i) & 15;
            const unsigned char* srcz = g_zh + ((size_t)buf * 16 + ci) * 16384;
            uint32_t sb = smem + (uint32_t)(i % NSTG) * ZSTG;
            #pragma unroll
            for (int k = 0; k < 2; ++k) {
                int j = tid + k * NTHR;
                cp16(sb + j * 16, srcz + (size_t)j * 16);
            }
            cp_commit();
        };

        float acc[4][4];
        #pragma unroll
        for (int ni = 0; ni < 4; ++ni)
            #pragma unroll
            for (int q = 0; q < 4; ++q) acc[ni][q] = 0.0f;

        // deep prologue: 5 chunks in flight before first compute
        issue(0); issue(1); issue(2); issue(3); issue(4);
        for (int i = 0; i < NCHL; ++i) {
            // exact wait ladder: group i must be complete
            if      (i <= 11) cp_wait<4>();
            else if (i == 12) cp_wait<3>();
            else if (i == 13) cp_wait<2>();
            else if (i == 14) cp_wait<1>();
            else              cp_wait<0>();
            __syncthreads();
            if (i + 5 < NCHL) issue(i + 5);   // slot (i+5)%6 consumed at i-1: free

            const int ci = (chl + i) & 15;
            const uint32_t zb  = smem + (uint32_t)(i % NSTG) * ZSTG;
            const uint32_t zhi = zb, zlo = zb + 8192;
            const uint32_t whi = smem + WOFF + (uint32_t)ci * 8192, wlo = whi + 4096;

            uint32_t ah[4], al[4], bh[4][2], bl[4][2];
            ldsm4(ah[0], ah[1], ah[2], ah[3], zhi + aoff);
            ldsm4(al[0], al[1], al[2], al[3], zlo + aoff);
            #pragma unroll
            for (int ni = 0; ni < 4; ++ni) {
                ldsm2(bh[ni][0], bh[ni][1], whi + boff[ni]);
                ldsm2(bl[ni][0], bl[ni][1], wlo + boff[ni]);
            }
            #pragma unroll
            for (int ni = 0; ni < 4; ++ni) {
                mma16816(acc[ni], ah[0], ah[1], ah[2], ah[3], bh[ni][0], bh[ni][1]);
                mma16816(acc[ni], ah[0], ah[1], ah[2], ah[3], bl[ni][0], bl[ni][1]);
                mma16816(acc[ni], al[0], al[1], al[2], al[3], bh[ni][0], bh[ni][1]);
            }
        }
        __syncthreads();   // all stage reads complete before pp aliases the region

        // ---- gather K-split partials (warp-private slices; stride 34 = aligned float2) ----
        {
            float* pp = pp_s + kslice * PP_SLICE;
            int r0 = mg * 16 + (lane >> 2);
            #pragma unroll
            for (int ni = 0; ni < 4; ++ni) {
                int c = ni * 8 + (lane & 3) * 2;
                *(float2*)&pp[r0 * PP_STRIDE + c]       = make_float2(acc[ni][0], acc[ni][1]);
                *(float2*)&pp[(r0 + 8) * PP_STRIDE + c] = make_float2(acc[ni][2], acc[ni][3]);
            }
        }
        __syncthreads();

        // ---- epilogue: 512 threads, 1 cell each; out-store deferred past the arrive ----
        float hval;
        {
            const int myl = len_s[b];
            const int bo34 = b * PP_STRIDE;
            float pre[4];
            #pragma unroll
            for (int g = 0; g < 4; ++g) {
                const int c = g * 8 + dd;
                pre[g] = pxr[g] + bias_s[c]
                       + pp_s[bo34 + c] + pp_s[PP_SLICE + bo34 + c]
                       + pp_s[2 * PP_SLICE + bo34 + c] + pp_s[3 * PP_SLICE + bo34 + c];
            }
            float ig = sigmoidf_(pre[0]), fg = sigmoidf_(pre[1]);
            float gg = tanhf(pre[2]),     og = sigmoidf_(pre[3]);
            float cn = fg * c_s[b * 8 + dd] + ig * gg;
            float h  = og * tanhf(cn);
            if (t >= myl) h = 0.0f;
            c_s[b * 8 + dd] = cn;
            __nv_bfloat16 hb = __float2bfloat16_rn(h);
            unsigned short hh = reinterpret_cast<unsigned short&>(hb);
            unsigned short hl = bf16hi(h - __bfloat162float(hb));
            hval = h;
            unsigned char* base = g_zh + ((size_t)(buf ^ 1) * 16 + chl) * 16384;
            uint32_t off = swz128((uint32_t)b * 128 + (uint32_t)kkb * 16) + (uint32_t)dd * 2;
            *(unsigned short*)(base + off)        = hh;
            *(unsigned short*)(base + 8192 + off) = hl;
        }
        __syncthreads();
        if (tid == 0) {        // producer arrive (post-sync tid0 fence covers all threads' h stores)
            __threadfence();
            unsigned long long my = atomicAdd(&g_bar, 1ULL);
            *tgt_s = (my / NCTA + 1ULL) * NCTA;
        }
        // output store: off the inter-CTA critical path
        out[((size_t)t * BATCH + b) * DHID + dbase + dd] = hval;
    }
}

extern "C" void kernel_launch(void* const* d_in, const int* in_sizes, int n_in,
                              void* d_out, int out_size) {
    const float* batch   = (const float*)d_in[0];
    const int*   lengths = (const int*)  d_in[1];
    const float* c0      = (const float*)d_in[2];
    const float* Wi = (const float*)d_in[3];
    const float* bi = (const float*)d_in[4];
    const float* Wf = (const float*)d_in[5];
    const float* bf = (const float*)d_in[6];
    const float* Wc = (const float*)d_in[7];
    const float* bc = (const float*)d_in[8];
    const float* Wo = (const float*)d_in[9];
    const float* bo = (const float*)d_in[10];
    float* out = (float*)d_out;

    cvt_x_kernel<<<TSTEPS * 16, 128>>>(batch);
    cvt_w_kernel<<<512 + NCTA * NCHL, 256>>>(Wi, Wf, Wc, Wo);

    cudaFuncSetAttribute(gemm_x_kernel, cudaFuncAttributeMaxDynamicSharedMemorySize, SMEM_PRE);
    gemm_x_kernel<<<dim3(32, 128), 256, SMEM_PRE>>>();

    cudaFuncSetAttribute(lstm_mma_kernel, cudaFuncAttributeMaxDynamicSharedMemorySize, SMEM_LOOP);
    lstm_mma_kernel<<<NCTA, NTHR, SMEM_LOOP>>>(lengths, c0, bi, bf, bc, bo, out);
}